// round 15
// baseline (speedup 1.0000x reference)
#include <cuda_runtime.h>
#include <math.h>

// Problem constants (fixed by the dataset)
#define NB 256      // batch (docs)
#define NL 512      // tokens per doc
#define ND 1024     // embedding dim
#define NT 64       // tiles per doc (8 tokens per tile)
// emb_table is (V+1, D) = (50001, 1024) float32

// Scratch (device globals — no allocation allowed)
__device__ float g_hpart[NB * 2 * ND];  // per-doc 2-way partial sums of emb rows
__device__ float g_v[NB * ND];          // v[b] = W_b @ mean(emb[b])

// ---------------------------------------------------------------------------
// Pass 1: partial sums of gathered embedding rows.  (EXACT R6/R1 version)
// ---------------------------------------------------------------------------
__global__ void k_hidden(const int* __restrict__ tokens,
                         const float* __restrict__ emb) {
    __shared__ int s_tok[256];
    const int b    = blockIdx.x >> 1;
    const int part = blockIdx.x & 1;
    const int t    = threadIdx.x;

    s_tok[t] = tokens[b * NL + part * 256 + t] + 1;   // +1 per reference lookup
    __syncthreads();

    const float4* emb4 = reinterpret_cast<const float4*>(emb);
    float4 acc = make_float4(0.f, 0.f, 0.f, 0.f);

#pragma unroll 4
    for (int l = 0; l < 256; ++l) {
        const int row = s_tok[l];
        float4 e = __ldg(&emb4[(size_t)row * 256 + t]);
        acc.x += e.x; acc.y += e.y; acc.z += e.z; acc.w += e.w;
    }
    reinterpret_cast<float4*>(g_hpart)[(b * 2 + part) * 256 + t] = acc;
}

// ---------------------------------------------------------------------------
// Small GEMM (R1 scalar): v[b,n] = sum_e hidden[b,e] * W[n,e].
// ---------------------------------------------------------------------------
__global__ void k_v(const float* __restrict__ W) {
    __shared__ float sA[32 * 34];   // [k][m], pad to 34
    __shared__ float sB[32 * 68];   // [k][n], pad to 68

    const int tid = threadIdx.x;
    const int bn0 = blockIdx.x * 64;
    const int bm0 = blockIdx.y * 32;
    const int tx  = tid & 15;
    const int ty  = tid >> 4;
    const int lm  = tid >> 3;
    const int lk  = tid & 7;

    const float4* W4  = reinterpret_cast<const float4*>(W);
    const float4* hp4 = reinterpret_cast<const float4*>(g_hpart);

    float acc[2][4] = {{0.f,0.f,0.f,0.f},{0.f,0.f,0.f,0.f}};

    for (int k0 = 0; k0 < 1024; k0 += 32) {
        {
            const int bb = bm0 + lm;
            float4 h0 = hp4[bb * 512 +       (k0 >> 2) + lk];
            float4 h1 = hp4[bb * 512 + 256 + (k0 >> 2) + lk];
            const float s = 1.0f / 512.0f;
            sA[(lk * 4 + 0) * 34 + lm] = (h0.x + h1.x) * s;
            sA[(lk * 4 + 1) * 34 + lm] = (h0.y + h1.y) * s;
            sA[(lk * 4 + 2) * 34 + lm] = (h0.z + h1.z) * s;
            sA[(lk * 4 + 3) * 34 + lm] = (h0.w + h1.w) * s;
        }
#pragma unroll
        for (int r = 0; r < 2; ++r) {
            const int n = lm + r * 32;
            float4 w = W4[(size_t)(bn0 + n) * 256 + (k0 >> 2) + lk];
            sB[(lk * 4 + 0) * 68 + n] = w.x;
            sB[(lk * 4 + 1) * 68 + n] = w.y;
            sB[(lk * 4 + 2) * 68 + n] = w.z;
            sB[(lk * 4 + 3) * 68 + n] = w.w;
        }
        __syncthreads();

#pragma unroll
        for (int k = 0; k < 32; ++k) {
            float2 a2 = *reinterpret_cast<const float2*>(&sA[k * 34 + ty * 2]);
            float4 b4 = *reinterpret_cast<const float4*>(&sB[k * 68 + tx * 4]);
            acc[0][0] += a2.x * b4.x; acc[0][1] += a2.x * b4.y;
            acc[0][2] += a2.x * b4.z; acc[0][3] += a2.x * b4.w;
            acc[1][0] += a2.y * b4.x; acc[1][1] += a2.y * b4.y;
            acc[1][2] += a2.y * b4.z; acc[1][3] += a2.y * b4.w;
        }
        __syncthreads();
    }

#pragma unroll
    for (int i = 0; i < 2; ++i) {
        const int row = bm0 + ty * 2 + i;
        float4 o = make_float4(acc[i][0], acc[i][1], acc[i][2], acc[i][3]);
        reinterpret_cast<float4*>(g_v)[row * 256 + (bn0 >> 2) + tx] = o;
    }
}

// ---------------------------------------------------------------------------
// Pass 2: CTA-wide tiled online softmax. 1 CTA/doc, 512 threads.
// Double-buffered 8-token tiles in dynamic smem (2 x 32 KB), NT=64 tiles.
// Per tile: load next tile (4x LDG.128/thread, streaming like k_hidden),
// 16 warps score 8 tokens from smem (2 warps/token), warp 0 computes the
// online-softmax scalars, all threads rescale+accumulate their 2 D-columns.
// ---------------------------------------------------------------------------
__global__ void __launch_bounds__(512, 2)
k_ct(const int* __restrict__ tokens, const float* __restrict__ emb,
     float* __restrict__ out) {
    extern __shared__ float tile[];   // [2][8][1024] floats = 64 KB
    __shared__ int   s_tok[512];
    __shared__ float s_part[8][2];
    __shared__ float s_w[8];
    __shared__ float s_cf[2];         // [0] = c this tile, [1] = 1/den at end

    const int b    = blockIdx.x;
    const int tid  = threadIdx.x;
    const int w    = tid >> 5;
    const int lane = tid & 31;
    const int row_s = w >> 1;         // token row this warp scores (0..7)
    const int half  = w & 1;          // which D-half of the dot

    s_tok[tid] = tokens[b * NL + tid] + 1;
    __syncthreads();

    const float4* emb4 = reinterpret_cast<const float4*>(emb);
    const float4* v4   = reinterpret_cast<const float4*>(g_v);
    float4* tile4 = reinterpret_cast<float4*>(tile);

    // score operand: lane's slice of v for (half)
    float4 vr[4];
#pragma unroll
    for (int i = 0; i < 4; ++i) vr[i] = v4[b * 256 + half * 128 + i * 32 + lane];

    float2 acc = make_float2(0.f, 0.f);   // this thread's 2 D-columns
    float m = -INFINITY, den = 0.f;       // meaningful in warp 0 (uniform)

    const int chunk = tid & 255;          // float4 chunk within a row
    const int rbase = tid >> 8;           // 0/1: which row of each it-pair

    // Prologue: load tile 0 into buf 0
    float4 r[4];
#pragma unroll
    for (int it = 0; it < 4; ++it) {
        const int row = it * 2 + rbase;
        r[it] = __ldg(&emb4[(size_t)s_tok[row] * 256 + chunk]);
    }
#pragma unroll
    for (int it = 0; it < 4; ++it) tile4[it * 512 + tid] = r[it];
    __syncthreads();

    for (int k = 0; k < NT; ++k) {
        const int buf = k & 1;

        // issue next tile's global loads (latency hidden under compute)
        if (k + 1 < NT) {
            const int j0 = (k + 1) * 8;
#pragma unroll
            for (int it = 0; it < 4; ++it) {
                const int row = j0 + it * 2 + rbase;
                r[it] = __ldg(&emb4[(size_t)s_tok[row] * 256 + chunk]);
            }
        }

        // score: warp w -> partial dot of token row_s, D-half half
        {
            const float4* tb = tile4 + buf * 2048 + row_s * 256 + half * 128 + lane;
            float s = 0.f;
#pragma unroll
            for (int i = 0; i < 4; ++i) {
                float4 e = tb[i * 32];
                s += e.x * vr[i].x + e.y * vr[i].y + e.z * vr[i].z + e.w * vr[i].w;
            }
#pragma unroll
            for (int o = 16; o; o >>= 1) s += __shfl_xor_sync(0xffffffffu, s, o);
            if (lane == 0) s_part[row_s][half] = s;
        }
        __syncthreads();

        // warp 0: online-softmax scalars for the 8 tokens
        if (w == 0) {
            float st = (lane < 8) ? s_part[lane][0] + s_part[lane][1] : -INFINITY;
            float mx = st;
#pragma unroll
            for (int o = 16; o; o >>= 1) mx = fmaxf(mx, __shfl_xor_sync(0xffffffffu, mx, o));
            const float m_new = fmaxf(m, mx);
            const float c = __expf(m - m_new);          // 0 on first tile
            float wt = (lane < 8) ? __expf(st - m_new) : 0.f;
            float sw = wt;
#pragma unroll
            for (int o = 16; o; o >>= 1) sw += __shfl_xor_sync(0xffffffffu, sw, o);
            den = den * c + sw;
            m = m_new;
            if (lane < 8) s_w[lane] = wt;
            if (lane == 0) s_cf[0] = c;
        }
        __syncthreads();

        // accumulate: each thread owns D-columns 2*tid, 2*tid+1
        {
            const float c = s_cf[0];
            const float* tf = tile + buf * 8192 + 2 * tid;
            acc.x *= c; acc.y *= c;
#pragma unroll
            for (int t = 0; t < 8; ++t) {
                float2 e = *reinterpret_cast<const float2*>(&tf[t * 1024]);
                const float wt = s_w[t];
                acc.x += wt * e.x; acc.y += wt * e.y;
            }
        }

        // stage next tile into the other buffer
        if (k + 1 < NT) {
#pragma unroll
            for (int it = 0; it < 4; ++it)
                tile4[(buf ^ 1) * 2048 + it * 512 + tid] = r[it];
        }
        __syncthreads();
    }

    if (tid == 0) s_cf[1] = 1.0f / den;
    __syncthreads();
    const float inv = s_cf[1];
    reinterpret_cast<float2*>(out + (size_t)b * ND)[tid] =
        make_float2(acc.x * inv, acc.y * inv);
}

// ---------------------------------------------------------------------------
extern "C" void kernel_launch(void* const* d_in, const int* in_sizes, int n_in,
                              void* d_out, int out_size) {
    const int*   tokens = (const int*)d_in[0];
    // d_in[1] = max_len (scalar, unused — fixed at 512)
    const float* emb    = (const float*)d_in[2];
    const float* W      = (const float*)d_in[3];
    float*       out    = (float*)d_out;

    const int tile_bytes = 2 * 8 * 1024 * (int)sizeof(float);  // 64 KB
    cudaFuncSetAttribute(k_ct, cudaFuncAttributeMaxDynamicSharedMemorySize,
                         tile_bytes);

    k_hidden<<<NB * 2, 256>>>(tokens, emb);
    k_v<<<dim3(16, 8), 256>>>(W);
    k_ct<<<NB, 512, tile_bytes>>>(tokens, emb, out);
}

// round 16
// speedup vs baseline: 1.3673x; 1.3673x over previous
#include <cuda_runtime.h>
#include <math.h>

// Problem constants (fixed by the dataset)
#define NB 256      // batch (docs)
#define NL 512      // tokens per doc
#define ND 1024     // embedding dim
// emb_table is (V+1, D) = (50001, 1024) float32

// Scratch (device globals — no allocation allowed)
__device__ float g_hpart[NB * 2 * ND];   // per-doc 2-way partial sums of emb rows
__device__ float g_v[NB * ND];           // v[b] = W_b @ mean(emb[b])
__device__ float g_pct[NB * 2 * ND];     // per-half-doc unnormalized ct partials
__device__ float g_meta[NB * 2 * 2];     // per-half-doc (M, den)

// ---------------------------------------------------------------------------
// Pass 1: partial sums of gathered embedding rows. R6 structure, unroll 8.
// ---------------------------------------------------------------------------
__global__ void k_hidden(const int* __restrict__ tokens,
                         const float* __restrict__ emb) {
    __shared__ int s_tok[256];
    const int b    = blockIdx.x >> 1;
    const int part = blockIdx.x & 1;
    const int t    = threadIdx.x;

    s_tok[t] = tokens[b * NL + part * 256 + t] + 1;   // +1 per reference lookup
    __syncthreads();

    const float4* emb4 = reinterpret_cast<const float4*>(emb);
    float4 acc = make_float4(0.f, 0.f, 0.f, 0.f);

#pragma unroll 8
    for (int l = 0; l < 256; ++l) {
        const int row = s_tok[l];
        float4 e = __ldg(&emb4[(size_t)row * 256 + t]);
        acc.x += e.x; acc.y += e.y; acc.z += e.z; acc.w += e.w;
    }
    reinterpret_cast<float4*>(g_hpart)[(b * 2 + part) * 256 + t] = acc;
}

// ---------------------------------------------------------------------------
// Small GEMM (R1 scalar): v[b,n] = sum_e hidden[b,e] * W[n,e].
// ---------------------------------------------------------------------------
__global__ void k_v(const float* __restrict__ W) {
    __shared__ float sA[32 * 34];   // [k][m], pad to 34
    __shared__ float sB[32 * 68];   // [k][n], pad to 68

    const int tid = threadIdx.x;
    const int bn0 = blockIdx.x * 64;
    const int bm0 = blockIdx.y * 32;
    const int tx  = tid & 15;
    const int ty  = tid >> 4;
    const int lm  = tid >> 3;
    const int lk  = tid & 7;

    const float4* W4  = reinterpret_cast<const float4*>(W);
    const float4* hp4 = reinterpret_cast<const float4*>(g_hpart);

    float acc[2][4] = {{0.f,0.f,0.f,0.f},{0.f,0.f,0.f,0.f}};

    for (int k0 = 0; k0 < 1024; k0 += 32) {
        {
            const int bb = bm0 + lm;
            float4 h0 = hp4[bb * 512 +       (k0 >> 2) + lk];
            float4 h1 = hp4[bb * 512 + 256 + (k0 >> 2) + lk];
            const float s = 1.0f / 512.0f;
            sA[(lk * 4 + 0) * 34 + lm] = (h0.x + h1.x) * s;
            sA[(lk * 4 + 1) * 34 + lm] = (h0.y + h1.y) * s;
            sA[(lk * 4 + 2) * 34 + lm] = (h0.z + h1.z) * s;
            sA[(lk * 4 + 3) * 34 + lm] = (h0.w + h1.w) * s;
        }
#pragma unroll
        for (int r = 0; r < 2; ++r) {
            const int n = lm + r * 32;
            float4 w = W4[(size_t)(bn0 + n) * 256 + (k0 >> 2) + lk];
            sB[(lk * 4 + 0) * 68 + n] = w.x;
            sB[(lk * 4 + 1) * 68 + n] = w.y;
            sB[(lk * 4 + 2) * 68 + n] = w.z;
            sB[(lk * 4 + 3) * 68 + n] = w.w;
        }
        __syncthreads();

#pragma unroll
        for (int k = 0; k < 32; ++k) {
            float2 a2 = *reinterpret_cast<const float2*>(&sA[k * 34 + ty * 2]);
            float4 b4 = *reinterpret_cast<const float4*>(&sB[k * 68 + tx * 4]);
            acc[0][0] += a2.x * b4.x; acc[0][1] += a2.x * b4.y;
            acc[0][2] += a2.x * b4.z; acc[0][3] += a2.x * b4.w;
            acc[1][0] += a2.y * b4.x; acc[1][1] += a2.y * b4.y;
            acc[1][2] += a2.y * b4.z; acc[1][3] += a2.y * b4.w;
        }
        __syncthreads();
    }

#pragma unroll
    for (int i = 0; i < 2; ++i) {
        const int row = bm0 + ty * 2 + i;
        float4 o = make_float4(acc[i][0], acc[i][1], acc[i][2], acc[i][3]);
        reinterpret_cast<float4*>(g_v)[row * 256 + (bn0 >> 2) + tx] = o;
    }
}

// ---------------------------------------------------------------------------
// Pass 2a: half-doc flash partials. 512 CTAs (2 per doc), 256 thr = 8 warps
// = 4 pairs; pair p handles tokens hh*256 + p*64 .. +63; half h owns
// D-components h*512..+511. Same inner loop as R6. Emits UNNORMALIZED
// partial (M_cta, den_cta, sum e^{s-M_cta} * e) per half-doc.
// (256,4) -> 32 warps/SM, 512 CTAs in <1 wave: k_hidden's geometry.
// ---------------------------------------------------------------------------
__global__ void __launch_bounds__(256, 4)
k_ct_part(const int* __restrict__ tokens, const float* __restrict__ emb) {
    __shared__ int   s_tok[256];
    __shared__ float s_ct[1024];
    __shared__ float s_ex[4][2][2];   // [pair][token parity][half]
    __shared__ float s_m[4];
    __shared__ float s_d[4];

    const int cta  = blockIdx.x;      // 0..511
    const int b    = cta >> 1;
    const int hh   = cta & 1;         // token half of the doc
    const int tid  = threadIdx.x;
    const int w    = tid >> 5;
    const int p    = w >> 1;          // pair 0..3
    const int h    = w & 1;           // D-half 0/1
    const int lane = tid & 31;

    s_tok[tid] = tokens[b * NL + hh * 256 + tid] + 1;
    s_ct[tid]        = 0.f;
    s_ct[tid + 256]  = 0.f;
    s_ct[tid + 512]  = 0.f;
    s_ct[tid + 768]  = 0.f;
    __syncthreads();

    const float4* emb4 = reinterpret_cast<const float4*>(emb);
    const float4* v4   = reinterpret_cast<const float4*>(g_v);

    // lane owns D-components d = h*512 + it*128 + lane*4 .. +3, it = 0..3
    float4 vr[4];
#pragma unroll
    for (int it = 0; it < 4; ++it) vr[it] = v4[b * 256 + h * 128 + it * 32 + lane];

    float4 nacc[4];
#pragma unroll
    for (int it = 0; it < 4; ++it) nacc[it] = make_float4(0.f, 0.f, 0.f, 0.f);

    float m   = -INFINITY;
    float den = 0.f;

    for (int j = 0; j < 64; ++j) {
        const int row = s_tok[p * 64 + j];
        const float4* q = emb4 + (size_t)row * 256 + h * 128 + lane;

        float4 e[4];
        float  s = 0.f;
#pragma unroll
        for (int it = 0; it < 4; ++it) {
            e[it] = q[it * 32];
            s += e[it].x * vr[it].x + e[it].y * vr[it].y
               + e[it].z * vr[it].z + e[it].w * vr[it].w;
        }
#pragma unroll
        for (int o = 16; o; o >>= 1) s += __shfl_xor_sync(0xffffffffu, s, o);

        if (lane == 0) s_ex[p][j & 1][h] = s;
        asm volatile("bar.sync %0, 64;" :: "r"(p + 1) : "memory");
        s = s_ex[p][j & 1][0] + s_ex[p][j & 1][1];

        const float m_new = fmaxf(m, s);
        const float c  = __expf(m - m_new);   // 1 when max unchanged, 0 on first
        const float wl = __expf(s - m_new);
        den = den * c + wl;
        if (c != 1.0f) {
#pragma unroll
            for (int it = 0; it < 4; ++it) {
                nacc[it].x *= c; nacc[it].y *= c;
                nacc[it].z *= c; nacc[it].w *= c;
            }
        }
#pragma unroll
        for (int it = 0; it < 4; ++it) {
            nacc[it].x += wl * e[it].x; nacc[it].y += wl * e[it].y;
            nacc[it].z += wl * e[it].z; nacc[it].w += wl * e[it].w;
        }
        m = m_new;
    }

    if (h == 0 && lane == 0) { s_m[p] = m; s_d[p] = den; }
    __syncthreads();

    float M = -INFINITY;
#pragma unroll
    for (int i = 0; i < 4; ++i) M = fmaxf(M, s_m[i]);
    float dg = 0.f;
#pragma unroll
    for (int i = 0; i < 4; ++i) dg += s_d[i] * __expf(s_m[i] - M);

    // UNNORMALIZED: rescale this pair's partial to the CTA max only
    const float sc = __expf(m - M);
#pragma unroll
    for (int it = 0; it < 4; ++it) {
        const int d0 = h * 512 + it * 128 + lane * 4;
        atomicAdd(&s_ct[d0 + 0], nacc[it].x * sc);
        atomicAdd(&s_ct[d0 + 1], nacc[it].y * sc);
        atomicAdd(&s_ct[d0 + 2], nacc[it].z * sc);
        atomicAdd(&s_ct[d0 + 3], nacc[it].w * sc);
    }
    __syncthreads();

    if (tid == 0) { g_meta[cta * 2 + 0] = M; g_meta[cta * 2 + 1] = dg; }
    g_pct[(size_t)cta * ND + tid]       = s_ct[tid];
    g_pct[(size_t)cta * ND + tid + 256] = s_ct[tid + 256];
    g_pct[(size_t)cta * ND + tid + 512] = s_ct[tid + 512];
    g_pct[(size_t)cta * ND + tid + 768] = s_ct[tid + 768];
}

// ---------------------------------------------------------------------------
// Pass 2b: combine the two half-doc partials. 256 CTAs x 256 thr, float4.
// ---------------------------------------------------------------------------
__global__ void k_combine(float* __restrict__ out) {
    const int b   = blockIdx.x;
    const int tid = threadIdx.x;

    const float M0 = g_meta[(b * 2 + 0) * 2 + 0];
    const float d0 = g_meta[(b * 2 + 0) * 2 + 1];
    const float M1 = g_meta[(b * 2 + 1) * 2 + 0];
    const float d1 = g_meta[(b * 2 + 1) * 2 + 1];

    const float M   = fmaxf(M0, M1);
    const float f0  = __expf(M0 - M);
    const float f1  = __expf(M1 - M);
    const float inv = 1.0f / (d0 * f0 + d1 * f1);

    const float4* p0 = reinterpret_cast<const float4*>(g_pct + (size_t)(b * 2 + 0) * ND);
    const float4* p1 = reinterpret_cast<const float4*>(g_pct + (size_t)(b * 2 + 1) * ND);
    float4 a = p0[tid];
    float4 c = p1[tid];
    float4 o;
    o.x = (a.x * f0 + c.x * f1) * inv;
    o.y = (a.y * f0 + c.y * f1) * inv;
    o.z = (a.z * f0 + c.z * f1) * inv;
    o.w = (a.w * f0 + c.w * f1) * inv;
    reinterpret_cast<float4*>(out + (size_t)b * ND)[tid] = o;
}

// ---------------------------------------------------------------------------
extern "C" void kernel_launch(void* const* d_in, const int* in_sizes, int n_in,
                              void* d_out, int out_size) {
    const int*   tokens = (const int*)d_in[0];
    // d_in[1] = max_len (scalar, unused — fixed at 512)
    const float* emb    = (const float*)d_in[2];
    const float* W      = (const float*)d_in[3];
    float*       out    = (float*)d_out;

    k_hidden<<<NB * 2, 256>>>(tokens, emb);
    k_v<<<dim3(16, 8), 256>>>(W);
    k_ct_part<<<NB * 2, 256>>>(tokens, emb);
    k_combine<<<NB, 256>>>(out);
}

// round 17
// speedup vs baseline: 1.4575x; 1.0660x over previous
#include <cuda_runtime.h>
#include <math.h>

// Problem constants (fixed by the dataset)
#define NB 256      // batch (docs)
#define NL 512      // tokens per doc
#define ND 1024     // embedding dim
// emb_table is (V+1, D) = (50001, 1024) float32

// Scratch (device globals — no allocation allowed)
__device__ float    g_hpart[NB * 2 * ND];   // per-doc 2-way partial sums
__device__ float    g_vpart[2][NB * ND];    // split-K halves of v[b]
__device__ float    g_pct[NB * 2 * ND];     // per-half-doc unnormalized partials
__device__ float    g_meta[NB * 2 * 2];     // per-half-doc (M, den)
__device__ unsigned g_cnt[NB];              // combine arbitration (self-resetting)

// ---------------------------------------------------------------------------
// Pass 1: partial sums of gathered embedding rows (unroll 8).
// ---------------------------------------------------------------------------
__global__ void k_hidden(const int* __restrict__ tokens,
                         const float* __restrict__ emb) {
    __shared__ int s_tok[256];
    const int b    = blockIdx.x >> 1;
    const int part = blockIdx.x & 1;
    const int t    = threadIdx.x;

    s_tok[t] = tokens[b * NL + part * 256 + t] + 1;   // +1 per reference lookup
    __syncthreads();

    const float4* emb4 = reinterpret_cast<const float4*>(emb);
    float4 acc = make_float4(0.f, 0.f, 0.f, 0.f);

#pragma unroll 8
    for (int l = 0; l < 256; ++l) {
        const int row = s_tok[l];
        float4 e = __ldg(&emb4[(size_t)row * 256 + t]);
        acc.x += e.x; acc.y += e.y; acc.z += e.z; acc.w += e.w;
    }
    reinterpret_cast<float4*>(g_hpart)[(b * 2 + part) * 256 + t] = acc;
}

// ---------------------------------------------------------------------------
// Small GEMM, split-K 2x: v_z[b,n] = sum_{e in half z} hidden[b,e] * W[n,e].
// Grid (16, 8, 2) = 256 CTAs; per-CTA K-loop halves to 16 iterations.
// ---------------------------------------------------------------------------
__global__ void k_v(const float* __restrict__ W) {
    __shared__ float sA[32 * 34];   // [k][m], pad to 34
    __shared__ float sB[32 * 68];   // [k][n], pad to 68

    const int tid = threadIdx.x;
    const int bn0 = blockIdx.x * 64;
    const int bm0 = blockIdx.y * 32;
    const int z   = blockIdx.z;     // K-half
    const int tx  = tid & 15;
    const int ty  = tid >> 4;
    const int lm  = tid >> 3;
    const int lk  = tid & 7;

    const float4* W4  = reinterpret_cast<const float4*>(W);
    const float4* hp4 = reinterpret_cast<const float4*>(g_hpart);

    float acc[2][4] = {{0.f,0.f,0.f,0.f},{0.f,0.f,0.f,0.f}};

    const int kbeg = z * 512;
    for (int k0 = kbeg; k0 < kbeg + 512; k0 += 32) {
        {
            const int bb = bm0 + lm;
            float4 h0 = hp4[bb * 512 +       (k0 >> 2) + lk];
            float4 h1 = hp4[bb * 512 + 256 + (k0 >> 2) + lk];
            const float s = 1.0f / 512.0f;
            sA[(lk * 4 + 0) * 34 + lm] = (h0.x + h1.x) * s;
            sA[(lk * 4 + 1) * 34 + lm] = (h0.y + h1.y) * s;
            sA[(lk * 4 + 2) * 34 + lm] = (h0.z + h1.z) * s;
            sA[(lk * 4 + 3) * 34 + lm] = (h0.w + h1.w) * s;
        }
#pragma unroll
        for (int r = 0; r < 2; ++r) {
            const int n = lm + r * 32;
            float4 w = W4[(size_t)(bn0 + n) * 256 + (k0 >> 2) + lk];
            sB[(lk * 4 + 0) * 68 + n] = w.x;
            sB[(lk * 4 + 1) * 68 + n] = w.y;
            sB[(lk * 4 + 2) * 68 + n] = w.z;
            sB[(lk * 4 + 3) * 68 + n] = w.w;
        }
        __syncthreads();

#pragma unroll
        for (int k = 0; k < 32; ++k) {
            float2 a2 = *reinterpret_cast<const float2*>(&sA[k * 34 + ty * 2]);
            float4 b4 = *reinterpret_cast<const float4*>(&sB[k * 68 + tx * 4]);
            acc[0][0] += a2.x * b4.x; acc[0][1] += a2.x * b4.y;
            acc[0][2] += a2.x * b4.z; acc[0][3] += a2.x * b4.w;
            acc[1][0] += a2.y * b4.x; acc[1][1] += a2.y * b4.y;
            acc[1][2] += a2.y * b4.z; acc[1][3] += a2.y * b4.w;
        }
        __syncthreads();
    }

#pragma unroll
    for (int i = 0; i < 2; ++i) {
        const int row = bm0 + ty * 2 + i;
        float4 o = make_float4(acc[i][0], acc[i][1], acc[i][2], acc[i][3]);
        reinterpret_cast<float4*>(g_vpart[z])[row * 256 + (bn0 >> 2) + tx] = o;
    }
}

// ---------------------------------------------------------------------------
// Pass 2: half-doc flash partials + fused last-CTA combine.
// 512 CTAs (2/doc), 256 thr = 4 pairs; pair p: tokens hh*256 + p*64..+63;
// half h owns D-components h*512..+511. vr = sum of split-K v halves.
// Last CTA of each doc (threadfence + atomic counter) merges and writes out.
// ---------------------------------------------------------------------------
__global__ void __launch_bounds__(256, 4)
k_ct_part(const int* __restrict__ tokens, const float* __restrict__ emb,
          float* __restrict__ out) {
    __shared__ int      s_tok[256];
    __shared__ float    s_ct[1024];
    __shared__ float    s_ex[4][2][2];   // [pair][token parity][half]
    __shared__ float    s_m[4];
    __shared__ float    s_d[4];
    __shared__ unsigned s_old;

    const int cta  = blockIdx.x;      // 0..511
    const int b    = cta >> 1;
    const int hh   = cta & 1;         // token half of the doc
    const int tid  = threadIdx.x;
    const int w    = tid >> 5;
    const int p    = w >> 1;          // pair 0..3
    const int h    = w & 1;           // D-half 0/1
    const int lane = tid & 31;

    s_tok[tid] = tokens[b * NL + hh * 256 + tid] + 1;
    s_ct[tid]        = 0.f;
    s_ct[tid + 256]  = 0.f;
    s_ct[tid + 512]  = 0.f;
    s_ct[tid + 768]  = 0.f;
    __syncthreads();

    const float4* emb4 = reinterpret_cast<const float4*>(emb);
    const float4* va   = reinterpret_cast<const float4*>(g_vpart[0]);
    const float4* vb   = reinterpret_cast<const float4*>(g_vpart[1]);

    // lane owns D-components d = h*512 + it*128 + lane*4 .. +3, it = 0..3
    float4 vr[4];
#pragma unroll
    for (int it = 0; it < 4; ++it) {
        const int idx = b * 256 + h * 128 + it * 32 + lane;
        float4 x = va[idx], y = vb[idx];
        vr[it] = make_float4(x.x + y.x, x.y + y.y, x.z + y.z, x.w + y.w);
    }

    float4 nacc[4];
#pragma unroll
    for (int it = 0; it < 4; ++it) nacc[it] = make_float4(0.f, 0.f, 0.f, 0.f);

    float m   = -INFINITY;
    float den = 0.f;

    for (int j = 0; j < 64; ++j) {
        const int row = s_tok[p * 64 + j];
        const float4* q = emb4 + (size_t)row * 256 + h * 128 + lane;

        float4 e[4];
        float  s = 0.f;
#pragma unroll
        for (int it = 0; it < 4; ++it) {
            e[it] = q[it * 32];
            s += e[it].x * vr[it].x + e[it].y * vr[it].y
               + e[it].z * vr[it].z + e[it].w * vr[it].w;
        }
#pragma unroll
        for (int o = 16; o; o >>= 1) s += __shfl_xor_sync(0xffffffffu, s, o);

        if (lane == 0) s_ex[p][j & 1][h] = s;
        asm volatile("bar.sync %0, 64;" :: "r"(p + 1) : "memory");
        s = s_ex[p][j & 1][0] + s_ex[p][j & 1][1];

        const float m_new = fmaxf(m, s);
        const float c  = __expf(m - m_new);   // 1 when max unchanged, 0 on first
        const float wl = __expf(s - m_new);
        den = den * c + wl;
        if (c != 1.0f) {
#pragma unroll
            for (int it = 0; it < 4; ++it) {
                nacc[it].x *= c; nacc[it].y *= c;
                nacc[it].z *= c; nacc[it].w *= c;
            }
        }
#pragma unroll
        for (int it = 0; it < 4; ++it) {
            nacc[it].x += wl * e[it].x; nacc[it].y += wl * e[it].y;
            nacc[it].z += wl * e[it].z; nacc[it].w += wl * e[it].w;
        }
        m = m_new;
    }

    if (h == 0 && lane == 0) { s_m[p] = m; s_d[p] = den; }
    __syncthreads();

    float M = -INFINITY;
#pragma unroll
    for (int i = 0; i < 4; ++i) M = fmaxf(M, s_m[i]);
    float dg = 0.f;
#pragma unroll
    for (int i = 0; i < 4; ++i) dg += s_d[i] * __expf(s_m[i] - M);

    // UNNORMALIZED partial, rescaled to this CTA's max
    const float sc = __expf(m - M);
#pragma unroll
    for (int it = 0; it < 4; ++it) {
        const int d0 = h * 512 + it * 128 + lane * 4;
        atomicAdd(&s_ct[d0 + 0], nacc[it].x * sc);
        atomicAdd(&s_ct[d0 + 1], nacc[it].y * sc);
        atomicAdd(&s_ct[d0 + 2], nacc[it].z * sc);
        atomicAdd(&s_ct[d0 + 3], nacc[it].w * sc);
    }
    __syncthreads();

    // publish partial + meta
    if (tid == 0) { g_meta[cta * 2 + 0] = M; g_meta[cta * 2 + 1] = dg; }
    float4* own4 = reinterpret_cast<float4*>(s_ct);
    reinterpret_cast<float4*>(g_pct + (size_t)cta * ND)[tid] = own4[tid];
    __threadfence();
    __syncthreads();
    if (tid == 0) s_old = atomicAdd(&g_cnt[b], 1u);
    __syncthreads();

    if (s_old == 1u) {                 // last CTA of this doc combines
        __threadfence();               // acquire the other CTA's writes
        const int other = cta ^ 1;
        const float Mo = g_meta[other * 2 + 0];
        const float Do = g_meta[other * 2 + 1];

        // canonical operand order: half 0 first (deterministic output)
        const float M0 = hh ? Mo : M,   D0 = hh ? Do : dg;
        const float M1 = hh ? M  : Mo,  D1 = hh ? dg : Do;
        const float MM = fmaxf(M0, M1);
        const float f0 = __expf(M0 - MM);
        const float f1 = __expf(M1 - MM);
        const float inv = 1.0f / (D0 * f0 + D1 * f1);
        const float fown = hh ? f1 : f0;
        const float foth = hh ? f0 : f1;

        float4 a = own4[tid];
        float4 c = reinterpret_cast<const float4*>(g_pct + (size_t)other * ND)[tid];
        float4 o;
        if (hh == 0) {
            o.x = (a.x * fown + c.x * foth) * inv;
            o.y = (a.y * fown + c.y * foth) * inv;
            o.z = (a.z * fown + c.z * foth) * inv;
            o.w = (a.w * fown + c.w * foth) * inv;
        } else {
            o.x = (c.x * foth + a.x * fown) * inv;
            o.y = (c.y * foth + a.y * fown) * inv;
            o.z = (c.z * foth + a.z * fown) * inv;
            o.w = (c.w * foth + a.w * fown) * inv;
        }
        reinterpret_cast<float4*>(out + (size_t)b * ND)[tid] = o;

        if (tid == 0) g_cnt[b] = 0u;   // reset for next graph replay
    }
}

// ---------------------------------------------------------------------------
extern "C" void kernel_launch(void* const* d_in, const int* in_sizes, int n_in,
                              void* d_out, int out_size) {
    const int*   tokens = (const int*)d_in[0];
    // d_in[1] = max_len (scalar, unused — fixed at 512)
    const float* emb    = (const float*)d_in[2];
    const float* W      = (const float*)d_in[3];
    float*       out    = (float*)d_out;

    k_hidden<<<NB * 2, 256>>>(tokens, emb);
    k_v<<<dim3(16, 8, 2), 256>>>(W);
    k_ct_part<<<NB * 2, 256>>>(tokens, emb, out);
}